// round 1
// baseline (speedup 1.0000x reference)
#include <cuda_runtime.h>
#include <math.h>

#define B_    8
#define L_    2048
#define DM    1000
#define ED    2000
#define NSTATE 8
#define DTR   63
#define NXP   79      /* DTR + 2*NSTATE */
#define NOUT  64
#define ROWS  (B_*L_) /* 16384 */

// ---------------- scratch (static device memory; no runtime alloc) ----------
__device__ __align__(128) float g_xn   [(size_t)ROWS*DM];
__device__ __align__(128) float g_xcin [(size_t)ROWS*ED];
__device__ __align__(128) float g_sz   [(size_t)ROWS*ED];
__device__ __align__(128) float g_xcs  [(size_t)ROWS*ED];
__device__ __align__(128) float g_delta[(size_t)ROWS*ED];
__device__ __align__(128) float g_dbc  [(size_t)ROWS*NXP];
__device__ __align__(128) float g_ybar [B_*ED];
__device__ __align__(128) float g_xbar [B_*DM];
__device__ __align__(128) float g_e    [B_*DM];

__device__ __forceinline__ float silu_f(float v) {
    return v / (1.f + __expf(-v));
}

// ---------------- rmsnorm -> xn ----------------
__global__ void rms_xn_kernel(const float* __restrict__ x, const float* __restrict__ w) {
    int row = blockIdx.x;
    int tid = threadIdx.x;
    const float* xr = x + (size_t)row * DM;
    float s = 0.f;
    for (int d = tid; d < DM; d += 256) { float v = xr[d]; s += v * v; }
    __shared__ float red[256];
    red[tid] = s; __syncthreads();
    for (int st = 128; st > 0; st >>= 1) {
        if (tid < st) red[tid] += red[tid + st];
        __syncthreads();
    }
    float rstd = rsqrtf(red[0] * (1.f / DM) + 1e-5f);
    float* o = g_xn + (size_t)row * DM;
    for (int d = tid; d < DM; d += 256) o[d] = xr[d] * rstd * w[d];
}

// ---------------- generic tiled SGEMM ----------------
// C(MxN) = A(MxK, lda) * B(KxN, ldb).  M must be a multiple of 128.
// mode 0: C1[gr*ldc+gc] = v
// mode 1: split at 2000: cols <2000 -> C1 (plain), cols >=2000 -> C2 = silu(v)
// mode 2: C1 = softplus(v + bias[gc])
template<bool VEC>
__global__ void __launch_bounds__(256, 2)
sgemm(const float* __restrict__ A, const float* __restrict__ B,
      int M, int N, int K, int lda, int ldb, int ldc,
      float* __restrict__ C1, float* __restrict__ C2,
      const float* __restrict__ bias, int mode)
{
    constexpr int BM = 128, BN = 128, BK = 16, TM = 8, TN = 8;
    __shared__ float As[BK][BM + 4];
    __shared__ float Bs[BK][BN];

    const int t = threadIdx.x;
    const int row0 = blockIdx.y * BM;
    const int col0 = blockIdx.x * BN;

    const int aRow = t >> 2;            // 0..63  (+64 second half)
    const int aCol = (t & 3) * 4;       // 0,4,8,12
    const int bRow = t >> 5;            // 0..7   (+8 second half)
    const int bCol = (t & 31) * 4;      // 0..124

    const int ty = t >> 4;              // 0..15
    const int tx = t & 15;              // 0..15

    float acc[TM][TN];
    #pragma unroll
    for (int i = 0; i < TM; i++)
        #pragma unroll
        for (int j = 0; j < TN; j++) acc[i][j] = 0.f;

    for (int k0 = 0; k0 < K; k0 += BK) {
        // ---- load A tile (BM x BK), store transposed ----
        #pragma unroll
        for (int s = 0; s < 2; s++) {
            int r  = aRow + s * 64;
            int gk = k0 + aCol;
            float4 v = make_float4(0.f, 0.f, 0.f, 0.f);
            const float* ap = A + (size_t)(row0 + r) * lda + gk;
            if (VEC) {
                if (gk < K) v = *reinterpret_cast<const float4*>(ap);
            } else {
                if (gk + 0 < K) v.x = ap[0];
                if (gk + 1 < K) v.y = ap[1];
                if (gk + 2 < K) v.z = ap[2];
                if (gk + 3 < K) v.w = ap[3];
            }
            As[aCol + 0][r] = v.x;
            As[aCol + 1][r] = v.y;
            As[aCol + 2][r] = v.z;
            As[aCol + 3][r] = v.w;
        }
        // ---- load B tile (BK x BN) ----
        #pragma unroll
        for (int s = 0; s < 2; s++) {
            int r  = bRow + s * 8;
            int gk = k0 + r;
            int gc = col0 + bCol;
            float4 v = make_float4(0.f, 0.f, 0.f, 0.f);
            const float* bp = B + (size_t)gk * ldb + gc;
            if (VEC) {
                if (gk < K && gc < N) v = *reinterpret_cast<const float4*>(bp);
            } else {
                if (gk < K) {
                    if (gc + 0 < N) v.x = bp[0];
                    if (gc + 1 < N) v.y = bp[1];
                    if (gc + 2 < N) v.z = bp[2];
                    if (gc + 3 < N) v.w = bp[3];
                }
            }
            *reinterpret_cast<float4*>(&Bs[r][bCol]) = v;
        }
        __syncthreads();

        #pragma unroll
        for (int kk = 0; kk < BK; kk++) {
            float ra[TM], rb[TN];
            const float4* a4 = reinterpret_cast<const float4*>(&As[kk][ty * TM]);
            float4 a0 = a4[0], a1 = a4[1];
            ra[0]=a0.x; ra[1]=a0.y; ra[2]=a0.z; ra[3]=a0.w;
            ra[4]=a1.x; ra[5]=a1.y; ra[6]=a1.z; ra[7]=a1.w;
            const float4* b4 = reinterpret_cast<const float4*>(&Bs[kk][tx * TN]);
            float4 b0 = b4[0], b1 = b4[1];
            rb[0]=b0.x; rb[1]=b0.y; rb[2]=b0.z; rb[3]=b0.w;
            rb[4]=b1.x; rb[5]=b1.y; rb[6]=b1.z; rb[7]=b1.w;
            #pragma unroll
            for (int i = 0; i < TM; i++)
                #pragma unroll
                for (int j = 0; j < TN; j++)
                    acc[i][j] = fmaf(ra[i], rb[j], acc[i][j]);
        }
        __syncthreads();
    }

    // ---- epilogue ----
    #pragma unroll
    for (int i = 0; i < TM; i++) {
        int gr = row0 + ty * TM + i;
        #pragma unroll
        for (int j = 0; j < TN; j++) {
            int gc = col0 + tx * TN + j;
            if (gc >= N) continue;
            float v = acc[i][j];
            if (mode == 0) {
                C1[(size_t)gr * ldc + gc] = v;
            } else if (mode == 1) {
                if (gc < 2000) C1[(size_t)gr * 2000 + gc] = v;
                else           C2[(size_t)gr * 2000 + (gc - 2000)] = silu_f(v);
            } else {
                float u = v + bias[gc];
                C1[(size_t)gr * ldc + gc] = (u > 20.f) ? u : log1pf(__expf(u));
            }
        }
    }
}

// ---------------- depthwise causal conv1d + silu ----------------
__global__ void conv_silu_kernel(const float* __restrict__ cw, const float* __restrict__ cb) {
    size_t idx = (size_t)blockIdx.x * blockDim.x + threadIdx.x;
    if (idx >= (size_t)ROWS * ED) return;
    int e = (int)(idx % ED);
    size_t bl = idx / ED;
    int l = (int)(bl % L_);
    float acc = cb[e];
    #pragma unroll
    for (int k = 0; k < 4; k++) {
        int ls = l - 3 + k;
        if (ls >= 0)
            acc = fmaf(g_xcin[idx + (size_t)(ls - l) * ED], cw[e * 4 + k], acc);
    }
    g_xcs[idx] = silu_f(acc);
}

// ---------------- selective scan, fused with y-epilogue + mean over L -------
// one thread per (b, e); 8-state recurrence in registers.
__global__ void scan_kernel(const float* __restrict__ A_log, const float* __restrict__ Dp) {
    int e = blockIdx.x * blockDim.x + threadIdx.x;
    int b = blockIdx.y;
    if (e >= ED) return;
    float A[NSTATE], h[NSTATE];
    #pragma unroll
    for (int n = 0; n < NSTATE; n++) {
        A[n] = -__expf(A_log[e * NSTATE + n]);
        h[n] = 0.f;
    }
    float dpe = Dp[e];
    float acc = 0.f;
    size_t base = ((size_t)b * L_) * ED + e;
    const float* dbcb = g_dbc + (size_t)b * L_ * NXP;
    for (int l = 0; l < L_; l++) {
        float d   = g_delta[base];
        float xv  = g_xcs[base];
        float szv = g_sz[base];
        const float* dbcr = dbcb + (size_t)l * NXP;
        float dx = d * xv;
        float y = 0.f;
        #pragma unroll
        for (int n = 0; n < NSTATE; n++) {
            float Bn = dbcr[DTR + n];
            float Cn = dbcr[DTR + NSTATE + n];
            float dA = __expf(d * A[n]);
            h[n] = fmaf(dA, h[n], dx * Bn);
            y = fmaf(h[n], Cn, y);
        }
        acc = fmaf(y + dpe * xv, szv, acc);
        base += ED;
    }
    g_ybar[b * ED + e] = acc * (1.0f / L_);
}

// ---------------- mean over L of residual x ----------------
__global__ void xbar_kernel(const float* __restrict__ x) {
    int idx = blockIdx.x * blockDim.x + threadIdx.x;
    if (idx >= B_ * DM) return;
    int b = idx / DM, d = idx % DM;
    const float* p = x + (size_t)b * L_ * DM + d;
    float s = 0.f;
    for (int l = 0; l < L_; l++) s += p[(size_t)l * DM];
    g_xbar[idx] = s * (1.f / L_);
}

// ---------------- e = xbar + ybar @ W_outp ----------------
__global__ void out_e_kernel(const float* __restrict__ W_outp) {
    int idx = blockIdx.x * blockDim.x + threadIdx.x;
    if (idx >= B_ * DM) return;
    int b = idx / DM, d = idx % DM;
    float acc = g_xbar[idx];
    const float* yb = g_ybar + b * ED;
    for (int e = 0; e < ED; e++)
        acc = fmaf(yb[e], W_outp[(size_t)e * DM + d], acc);
    g_e[idx] = acc;
}

// ---------------- h = elu(tanh(e @ W_fc + b_fc)) -> out[0:8000] -------------
__global__ void out_h_kernel(const float* __restrict__ W_fc, const float* __restrict__ b_fc,
                             float* __restrict__ out) {
    int idx = blockIdx.x * blockDim.x + threadIdx.x;
    if (idx >= B_ * DM) return;
    int b = idx / DM, d = idx % DM;
    float acc = b_fc[d];
    const float* er = g_e + b * DM;
    for (int k = 0; k < DM; k++)
        acc = fmaf(er[k], W_fc[(size_t)k * DM + d], acc);
    float th = tanhf(acc);
    out[idx] = (th > 0.f) ? th : expm1f(th);
}

// ---------------- mu / sigma heads ----------------
__global__ void out_musig_kernel(const float* __restrict__ W_mu, const float* __restrict__ b_mu,
                                 const float* __restrict__ W_sig, const float* __restrict__ b_sig,
                                 float* __restrict__ out) {
    int idx = blockIdx.x * blockDim.x + threadIdx.x;
    if (idx >= B_ * 2 * NOUT) return;
    int b = idx / (2 * NOUT);
    int r = idx % (2 * NOUT);
    const float* h = out + b * DM;   // h written by out_h_kernel
    if (r < NOUT) {
        float acc = b_mu[r];
        for (int k = 0; k < DM; k++)
            acc = fmaf(h[k], W_mu[(size_t)k * NOUT + r], acc);
        out[B_ * DM + b * NOUT + r] = acc;
    } else {
        int j = r - NOUT;
        float acc = b_sig[j];
        for (int k = 0; k < DM; k++)
            acc = fmaf(h[k], W_sig[(size_t)k * NOUT + j], acc);
        float el = (acc > 0.f) ? acc : expm1f(acc);
        out[B_ * DM + B_ * NOUT + b * NOUT + j] = el + 1.0f + 1e-14f;
    }
}

// ---------------- launcher ----------------
extern "C" void kernel_launch(void* const* d_in, const int* in_sizes, int n_in,
                              void* d_out, int out_size) {
    (void)in_sizes; (void)n_in; (void)out_size;
    const float* x      = (const float*)d_in[0];
    const float* w_norm = (const float*)d_in[1];
    const float* W_in   = (const float*)d_in[2];
    const float* conv_w = (const float*)d_in[3];
    const float* conv_b = (const float*)d_in[4];
    const float* W_xproj= (const float*)d_in[5];
    const float* W_dt   = (const float*)d_in[6];
    const float* b_dt   = (const float*)d_in[7];
    const float* A_log  = (const float*)d_in[8];
    const float* Dp     = (const float*)d_in[9];
    const float* W_outp = (const float*)d_in[10];
    const float* W_fc   = (const float*)d_in[11];
    const float* b_fc   = (const float*)d_in[12];
    const float* W_mu   = (const float*)d_in[13];
    const float* b_mu   = (const float*)d_in[14];
    const float* W_sig  = (const float*)d_in[15];
    const float* b_sig  = (const float*)d_in[16];
    float* out = (float*)d_out;

    float *p_xn, *p_xcin, *p_sz, *p_xcs, *p_delta, *p_dbc;
    cudaGetSymbolAddress((void**)&p_xn,    g_xn);
    cudaGetSymbolAddress((void**)&p_xcin,  g_xcin);
    cudaGetSymbolAddress((void**)&p_sz,    g_sz);
    cudaGetSymbolAddress((void**)&p_xcs,   g_xcs);
    cudaGetSymbolAddress((void**)&p_delta, g_delta);
    cudaGetSymbolAddress((void**)&p_dbc,   g_dbc);

    // 1) rmsnorm
    rms_xn_kernel<<<ROWS, 256>>>(x, w_norm);

    // 2) xz = xn @ W_in  (split: xc | silu(z))
    {
        dim3 grid((2 * ED + 127) / 128, ROWS / 128);
        sgemm<true><<<grid, 256>>>(p_xn, W_in, ROWS, 2 * ED, DM, DM, 2 * ED, 0,
                                   p_xcin, p_sz, nullptr, 1);
    }

    // 3) depthwise causal conv + silu
    {
        size_t total = (size_t)ROWS * ED;
        conv_silu_kernel<<<(unsigned)((total + 255) / 256), 256>>>(conv_w, conv_b);
    }

    // 4) dbc = xcs @ W_xproj  [ROWS x 79]
    {
        dim3 grid(1, ROWS / 128);
        sgemm<false><<<grid, 256>>>(p_xcs, W_xproj, ROWS, NXP, ED, ED, NXP, NXP,
                                    p_dbc, nullptr, nullptr, 0);
    }

    // 5) delta = softplus(dt @ W_dt + b_dt)  [ROWS x 2000]
    {
        dim3 grid((ED + 127) / 128, ROWS / 128);
        sgemm<false><<<grid, 256>>>(p_dbc, W_dt, ROWS, ED, DTR, NXP, ED, ED,
                                    p_delta, nullptr, b_dt, 2);
    }

    // 6) selective scan fused with y epilogue + mean over L
    {
        dim3 grid((ED + 255) / 256, B_);
        scan_kernel<<<grid, 256>>>(A_log, Dp);
    }

    // 7) xbar = mean_L(x)
    xbar_kernel<<<(B_ * DM + 255) / 256, 256>>>(x);

    // 8) e = xbar + ybar @ W_outp
    out_e_kernel<<<(B_ * DM + 255) / 256, 256>>>(W_outp);

    // 9) h = elu(tanh(e @ W_fc + b_fc))
    out_h_kernel<<<(B_ * DM + 255) / 256, 256>>>(W_fc, b_fc, out);

    // 10) mu, sigma
    out_musig_kernel<<<(B_ * 2 * NOUT + 255) / 256, 256>>>(W_mu, b_mu, W_sig, b_sig, out);
}